// round 1
// baseline (speedup 1.0000x reference)
#include <cuda_runtime.h>
#include <math.h>

// ---------------- problem constants ----------------
#define DD    768
#define FF    3072
#define NE    8
#define NB    2
#define NL    1024
#define NTOK  2048          // NB*NL
#define NH    12
#define HD    64
#define WINW  128
#define NOUT  (NTOK*DD)

// ---------------- device scratch (no runtime allocs allowed) ----------------
__device__ float g_K[NE*NTOK*DD];     // [e][b][l][d]   50.3 MB
__device__ float g_V[NE*NTOK*DD];     // 50.3 MB
__device__ float g_Q[NTOK*DD];
__device__ float g_attn[NTOK*DD];
__device__ float g_Hb[NTOK*FF];       // 25.2 MB
__device__ float g_Y[NTOK*DD];
__device__ float g_kbar[NE*NB*DD];    // mean key per (e,b), head-major in d
__device__ int   g_idx[NTOK];
__device__ int   g_sorted[NTOK];
__device__ int   g_counts[NE];
__device__ int   g_cursor[NE];
__device__ int   g_offs[NE+1];
__device__ float g_Psum[NE];

// ---------------- init ----------------
__global__ void init_k() {
    int t = threadIdx.x;
    if (t < NE) { g_counts[t] = 0; g_Psum[t] = 0.f; }
}

// ---------------- router: logits, softmax, argmax, P accumulation ----------------
__global__ __launch_bounds__(256) void router_k(const float* __restrict__ x,
                                                const float* __restrict__ gw) {
    int gtid = blockIdx.x * 256 + threadIdx.x;
    int tok  = gtid >> 5;
    int lane = gtid & 31;
    if (tok >= NTOK) return;
    const float* xr = x + (size_t)tok * DD;
    float acc[NE];
#pragma unroll
    for (int e = 0; e < NE; e++) acc[e] = 0.f;
    for (int d = lane; d < DD; d += 32) {
        float xv = xr[d];
        const float* g = gw + (size_t)d * NE;
#pragma unroll
        for (int e = 0; e < NE; e++) acc[e] += xv * g[e];
    }
#pragma unroll
    for (int e = 0; e < NE; e++)
#pragma unroll
        for (int off = 16; off; off >>= 1)
            acc[e] += __shfl_xor_sync(0xffffffffu, acc[e], off);
    if (lane == 0) {
        float l[NE]; float mx = -1e30f;
#pragma unroll
        for (int e = 0; e < NE; e++) { l[e] = acc[e] * 0.5f; mx = fmaxf(mx, l[e]); }
        int best = 0; float bv = l[0];
#pragma unroll
        for (int e = 1; e < NE; e++) if (l[e] > bv) { bv = l[e]; best = e; }
        g_idx[tok] = best;
        atomicAdd(&g_counts[best], 1);
        float p[NE]; float se = 0.f;
#pragma unroll
        for (int e = 0; e < NE; e++) { p[e] = expf(l[e] - mx); se += p[e]; }
        float inv = 1.f / se;
#pragma unroll
        for (int e = 0; e < NE; e++) atomicAdd(&g_Psum[e], p[e] * inv);
    }
}

// ---------------- offsets + aux loss ----------------
__global__ void offs_k(float* __restrict__ dout, long long out_size) {
    if (threadIdx.x == 0 && blockIdx.x == 0) {
        int o = 0;
        for (int e = 0; e < NE; e++) { g_offs[e] = o; g_cursor[e] = o; o += g_counts[e]; }
        g_offs[NE] = o;
        float aux = 0.f;
        for (int e = 0; e < NE; e++) aux += (float)g_counts[e] * g_Psum[e];
        aux *= (float)NE / ((float)NTOK * (float)NTOK);
        if (out_size > (long long)NOUT) dout[NOUT] = aux;
    }
}

// ---------------- token scatter (grouping by expert) ----------------
__global__ void scatter_k() {
    int t = blockIdx.x * 256 + threadIdx.x;
    if (t < NTOK) {
        int e = g_idx[t];
        int p = atomicAdd(&g_cursor[e], 1);
        g_sorted[p] = t;
    }
}

// ---------------- generic (optionally gathered/grouped) fp32 GEMM ----------------
// C[tok] = A[tok] @ B_e ; rows gathered through sorted/offs if provided.
// Tile 64x64x16, 256 threads, 4x4 microtile.
__global__ __launch_bounds__(256) void gemm_grouped(
    const float* __restrict__ A, int lda,
    const float* __restrict__ B0, size_t strideB, int ldb,
    float* __restrict__ C, int ldc, size_t strideC,
    int K,
    const int* __restrict__ sorted, const int* __restrict__ offs)
{
    int e = blockIdx.z;
    int cnt; const int* rmap;
    if (offs) { int s = offs[e]; cnt = offs[e+1] - s; rmap = sorted + s; }
    else      { cnt = NTOK; rmap = nullptr; }
    int m0 = blockIdx.y * 64;
    if (m0 >= cnt) return;
    int n0 = blockIdx.x * 64;
    const float* Bw = B0 + strideB * (size_t)e;
    float* Cb = C + strideC * (size_t)e;

    __shared__ float As[16][68];
    __shared__ float Bs[16][68];
    int tid = threadIdx.x;
    int tx = tid & 15, ty = tid >> 4;
    int lm = tid >> 2, lk = (tid & 3) * 4;       // A loader: row lm, k-chunk lk
    int lbk = tid >> 4, lbn = (tid & 15) * 4;    // B loader: row lbk, n-chunk lbn

    const float* Arow = nullptr;
    {
        int ra = m0 + lm;
        if (ra < cnt) {
            int tok = rmap ? rmap[ra] : ra;
            Arow = A + (size_t)tok * lda;
        }
    }

    float acc[4][4];
#pragma unroll
    for (int i = 0; i < 4; i++)
#pragma unroll
        for (int j = 0; j < 4; j++) acc[i][j] = 0.f;

    for (int k0 = 0; k0 < K; k0 += 16) {
        float4 av = Arow ? *(const float4*)(Arow + k0 + lk) : make_float4(0.f,0.f,0.f,0.f);
        As[lk+0][lm] = av.x; As[lk+1][lm] = av.y; As[lk+2][lm] = av.z; As[lk+3][lm] = av.w;
        *(float4*)&Bs[lbk][lbn] = *(const float4*)(Bw + (size_t)(k0 + lbk) * ldb + n0 + lbn);
        __syncthreads();
#pragma unroll
        for (int kk = 0; kk < 16; kk++) {
            float4 a = *(const float4*)&As[kk][ty*4];
            float4 b = *(const float4*)&Bs[kk][tx*4];
            float aa[4] = {a.x, a.y, a.z, a.w};
            float bb[4] = {b.x, b.y, b.z, b.w};
#pragma unroll
            for (int i = 0; i < 4; i++)
#pragma unroll
                for (int j = 0; j < 4; j++) acc[i][j] += aa[i] * bb[j];
        }
        __syncthreads();
    }
#pragma unroll
    for (int i = 0; i < 4; i++) {
        int r = m0 + ty*4 + i;
        if (r < cnt) {
            int tok = rmap ? rmap[r] : r;
            float* Cr = Cb + (size_t)tok * ldc + n0 + tx*4;
#pragma unroll
            for (int j = 0; j < 4; j++) Cr[j] = acc[i][j];
        }
    }
}

// ---------------- fused SwiGLU GEMM: H = silu(A@W1) * (A@VG), grouped/gathered ----------------
__global__ __launch_bounds__(256) void gemm_swiglu(
    const float* __restrict__ A,
    const float* __restrict__ W1g, const float* __restrict__ VGg,
    float* __restrict__ C)
{
    int e = blockIdx.z;
    int s = g_offs[e];
    int cnt = g_offs[e+1] - s;
    int m0 = blockIdx.y * 64;
    if (m0 >= cnt) return;
    int n0 = blockIdx.x * 64;
    const float* B1 = W1g + (size_t)e * DD * FF;
    const float* B2 = VGg + (size_t)e * DD * FF;
    const int* rmap = g_sorted + s;

    __shared__ float As[16][68];
    __shared__ float Bs1[16][68];
    __shared__ float Bs2[16][68];
    int tid = threadIdx.x;
    int tx = tid & 15, ty = tid >> 4;
    int lm = tid >> 2, lk = (tid & 3) * 4;
    int lbk = tid >> 4, lbn = (tid & 15) * 4;

    const float* Arow = nullptr;
    {
        int ra = m0 + lm;
        if (ra < cnt) Arow = A + (size_t)rmap[ra] * DD;
    }

    float acc1[4][4], acc2[4][4];
#pragma unroll
    for (int i = 0; i < 4; i++)
#pragma unroll
        for (int j = 0; j < 4; j++) { acc1[i][j] = 0.f; acc2[i][j] = 0.f; }

    for (int k0 = 0; k0 < DD; k0 += 16) {
        float4 av = Arow ? *(const float4*)(Arow + k0 + lk) : make_float4(0.f,0.f,0.f,0.f);
        As[lk+0][lm] = av.x; As[lk+1][lm] = av.y; As[lk+2][lm] = av.z; As[lk+3][lm] = av.w;
        *(float4*)&Bs1[lbk][lbn] = *(const float4*)(B1 + (size_t)(k0 + lbk) * FF + n0 + lbn);
        *(float4*)&Bs2[lbk][lbn] = *(const float4*)(B2 + (size_t)(k0 + lbk) * FF + n0 + lbn);
        __syncthreads();
#pragma unroll
        for (int kk = 0; kk < 16; kk++) {
            float4 a  = *(const float4*)&As[kk][ty*4];
            float4 b1 = *(const float4*)&Bs1[kk][tx*4];
            float4 b2 = *(const float4*)&Bs2[kk][tx*4];
            float aa[4]  = {a.x, a.y, a.z, a.w};
            float bb1[4] = {b1.x, b1.y, b1.z, b1.w};
            float bb2[4] = {b2.x, b2.y, b2.z, b2.w};
#pragma unroll
            for (int i = 0; i < 4; i++)
#pragma unroll
                for (int j = 0; j < 4; j++) {
                    acc1[i][j] += aa[i] * bb1[j];
                    acc2[i][j] += aa[i] * bb2[j];
                }
        }
        __syncthreads();
    }
#pragma unroll
    for (int i = 0; i < 4; i++) {
        int r = m0 + ty*4 + i;
        if (r < cnt) {
            int tok = rmap[r];
            float* Cr = C + (size_t)tok * FF + n0 + tx*4;
#pragma unroll
            for (int j = 0; j < 4; j++) {
                float z = acc1[i][j];
                Cr[j] = z / (1.f + expf(-z)) * acc2[i][j];   // silu(z)*gate
            }
        }
    }
}

// ---------------- mean key per (e,b): kbar = mean_j K[e,b,j,:] ----------------
__global__ void kbar_k() {
    int eb = blockIdx.x;                       // 0..15  (e*NB+b)
    const float* Kb = g_K + (size_t)eb * NL * DD;
    for (int d = threadIdx.x; d < DD; d += blockDim.x) {
        float s0 = 0.f, s1 = 0.f, s2 = 0.f, s3 = 0.f;
        for (int j = 0; j < NL; j += 4) {
            s0 += Kb[(size_t)(j+0)*DD + d];
            s1 += Kb[(size_t)(j+1)*DD + d];
            s2 += Kb[(size_t)(j+2)*DD + d];
            s3 += Kb[(size_t)(j+3)*DD + d];
        }
        g_kbar[(size_t)eb * DD + d] = (s0 + s1 + s2 + s3) * (1.f / (float)NL);
    }
}

// ---------------- sliding-window attention with Reynolds modulation ----------------
// One block per token; 12 warps = 12 heads.
__global__ __launch_bounds__(384) void attn_k() {
    int token = blockIdx.x;
    int b = token >> 10;
    int t = token & (NL - 1);
    int e = g_idx[token];

    __shared__ float qs[DD];
    __shared__ float sc[NH][WINW + 4];
    __shared__ float mh[NH], invs[NH];

    int tid = threadIdx.x, lane = tid & 31, w = tid >> 5;   // w = head
    for (int d = tid; d < DD; d += 384) qs[d] = g_Q[(size_t)token * DD + d];
    __syncthreads();

    int jlo = (t >= WINW - 1) ? t - (WINW - 1) : 0;
    int nj  = t - jlo + 1;
    size_t ebbase = (size_t)(e * NB + b) * NL * DD;
    const float* Kb = g_K + ebbase;

    int h = w;
    float q0 = qs[h*64 + lane*2], q1 = qs[h*64 + lane*2 + 1];

    // raw scores over the window
    for (int jj = 0; jj < nj; jj++) {
        const float* kr = Kb + (size_t)(jlo + jj) * DD + h*64 + lane*2;
        float p = q0 * kr[0] + q1 * kr[1];
#pragma unroll
        for (int off = 16; off; off >>= 1) p += __shfl_xor_sync(0xffffffffu, p, off);
        if (lane == 0) sc[h][jj] = p * 0.125f;
    }
    // full-row mean via mean key (linearity of dot)
    {
        const float* kb = g_kbar + (size_t)(e * NB + b) * DD + h*64 + lane*2;
        float p = q0 * kb[0] + q1 * kb[1];
#pragma unroll
        for (int off = 16; off; off >>= 1) p += __shfl_xor_sync(0xffffffffu, p, off);
        if (lane == 0) mh[h] = p * 0.125f;
    }
    __syncthreads();

    // Reynolds modulation + softmax over valid window
    float m = mh[h];
    float mx = -1e30f;
    for (int jj = lane; jj < nj; jj += 32) {
        float sv = sc[h][jj];
        float sig = 1.f / (1.f + __expf(-sv));
        float sp = sv + 0.1f * sv - 0.1f * sig * sig - 0.1f * fabsf(sv - m);
        sc[h][jj] = sp;
        mx = fmaxf(mx, sp);
    }
#pragma unroll
    for (int off = 16; off; off >>= 1) mx = fmaxf(mx, __shfl_xor_sync(0xffffffffu, mx, off));
    float sum = 0.f;
    for (int jj = lane; jj < nj; jj += 32) {
        float pexp = __expf(sc[h][jj] - mx);
        sc[h][jj] = pexp;
        sum += pexp;
    }
#pragma unroll
    for (int off = 16; off; off >>= 1) sum += __shfl_xor_sync(0xffffffffu, sum, off);
    if (lane == 0) invs[h] = 1.f / sum;
    __syncthreads();

    // out = attn @ V (coalesced over d)
    const float* Vb = g_V + ebbase;
    for (int od = tid; od < DD; od += 384) {
        int hh = od >> 6;
        float acc = 0.f;
        for (int jj = 0; jj < nj; jj++)
            acc += sc[hh][jj] * Vb[(size_t)(jlo + jj) * DD + od];
        g_attn[(size_t)token * DD + od] = acc * invs[hh];
    }
}

// ---------------- launch ----------------
extern "C" void kernel_launch(void* const* d_in, const int* in_sizes, int n_in,
                              void* d_out, int out_size) {
    const float* x      = (const float*)d_in[0];
    const float* gate_w = (const float*)d_in[1];
    const float* q_w    = (const float*)d_in[2];
    const float* k_w    = (const float*)d_in[3];
    const float* v_w    = (const float*)d_in[4];
    const float* w1     = (const float*)d_in[5];
    const float* vg     = (const float*)d_in[6];
    const float* w2     = (const float*)d_in[7];
    const float* out_w  = (const float*)d_in[8];
    float* out = (float*)d_out;

    void *pK, *pV, *pQ, *pA, *pH, *pY, *pS, *pO;
    cudaGetSymbolAddress(&pK, g_K);
    cudaGetSymbolAddress(&pV, g_V);
    cudaGetSymbolAddress(&pQ, g_Q);
    cudaGetSymbolAddress(&pA, g_attn);
    cudaGetSymbolAddress(&pH, g_Hb);
    cudaGetSymbolAddress(&pY, g_Y);
    cudaGetSymbolAddress(&pS, g_sorted);
    cudaGetSymbolAddress(&pO, g_offs);
    const int* sortedp = (const int*)pS;
    const int* offsp   = (const int*)pO;

    init_k<<<1, 32>>>();
    router_k<<<NTOK / 8, 256>>>(x, gate_w);
    offs_k<<<1, 32>>>(out, (long long)out_size);
    scatter_k<<<NTOK / 256, 256>>>();

    // K and V for ALL experts (dense batched)
    gemm_grouped<<<dim3(DD/64, NTOK/64, NE), 256>>>(
        x, DD, k_w, (size_t)DD*DD, DD, (float*)pK, DD, (size_t)NTOK*DD, DD,
        nullptr, nullptr);
    gemm_grouped<<<dim3(DD/64, NTOK/64, NE), 256>>>(
        x, DD, v_w, (size_t)DD*DD, DD, (float*)pV, DD, (size_t)NTOK*DD, DD,
        nullptr, nullptr);
    kbar_k<<<NE * NB, 256>>>();

    // Q only for the routed expert (gathered/grouped)
    gemm_grouped<<<dim3(DD/64, NTOK/64, NE), 256>>>(
        x, DD, q_w, (size_t)DD*DD, DD, (float*)pQ, DD, 0, DD,
        sortedp, offsp);

    attn_k<<<NTOK, 384>>>();

    // SwiGLU up-projection (fused dual GEMM, grouped)
    gemm_swiglu<<<dim3(FF/64, NTOK/64, NE), 256>>>(
        (const float*)pA, w1, vg, (float*)pH);

    // down projection (grouped)
    gemm_grouped<<<dim3(DD/64, NTOK/64, NE), 256>>>(
        (const float*)pH, FF, w2, (size_t)FF*DD, DD, (float*)pY, DD, 0, FF,
        sortedp, offsp);

    // final output projection (dense) -> d_out
    gemm_grouped<<<dim3(DD/64, NTOK/64, 1), 256>>>(
        (const float*)pY, DD, out_w, 0, DD, out, DD, 0, DD,
        nullptr, nullptr);
}

// round 3
// speedup vs baseline: 2.1510x; 2.1510x over previous
#include <cuda_runtime.h>
#include <math.h>
#include <stdint.h>

// ---------------- problem constants ----------------
#define DD    768
#define FF    3072
#define NE    8
#define NB    2
#define NL    1024
#define NTOK  2048
#define NH    12
#define HD    64
#define WINW  128
#define NOUT  (NTOK*DD)

// ---------------- device scratch ----------------
__device__ float g_K[NE*NTOK*DD];
__device__ float g_V[NE*NTOK*DD];
__device__ float g_Q[NTOK*DD];
__device__ float g_attn[NTOK*DD];
__device__ float g_Hb[NTOK*FF];
__device__ float g_Y[NTOK*DD];
__device__ float g_xc[NTOK*DD];       // x pre-rounded to tf32 (RN)
__device__ float g_kbar[NE*NB*DD];
__device__ int   g_idx[NTOK];
__device__ int   g_sorted[NTOK];
__device__ int   g_counts[NE];
__device__ int   g_cursor[NE];
__device__ int   g_offs[NE+1];
__device__ float g_Psum[NE];
// transposed weights [N][K] per expert, tf32-rounded
__device__ float g_qT[NE*DD*DD];
__device__ float g_kT[NE*DD*DD];
__device__ float g_vT[NE*DD*DD];
__device__ float g_w1T[NE*FF*DD];
__device__ float g_vgT[NE*FF*DD];
__device__ float g_w2T[NE*DD*FF];
__device__ float g_outT[DD*DD];

// ---------------- PTX helpers (baseline PTX only; no sm_103a-suffixed ops) ----------------
__device__ __forceinline__ uint32_t smem_u32(const void* p) {
    uint32_t a;
    asm("{ .reg .u64 t; cvta.to.shared.u64 t, %1; cvt.u32.u64 %0, t; }" : "=r"(a) : "l"(p));
    return a;
}
__device__ __forceinline__ void cp16(uint32_t s, const float* g) {
    asm volatile("cp.async.cg.shared.global [%0], [%1], 16;" :: "r"(s), "l"(g) : "memory");
}
__device__ __forceinline__ void cp_commit() {
    asm volatile("cp.async.commit_group;" ::: "memory");
}
template<int N> __device__ __forceinline__ void cp_wait() {
    asm volatile("cp.async.wait_group %0;" :: "n"(N) : "memory");
}
__device__ __forceinline__ float rntf(float v) {
    uint32_t o;
    asm("cvt.rna.tf32.f32 %0, %1;" : "=r"(o) : "f"(v));
    return __uint_as_float(o);
}
__device__ __forceinline__ void mma8(float* c, const uint32_t* a, const uint32_t* b) {
    asm volatile("mma.sync.aligned.m16n8k8.row.col.f32.tf32.tf32.f32 "
        "{%0,%1,%2,%3}, {%4,%5,%6,%7}, {%8,%9}, {%0,%1,%2,%3};"
        : "+f"(c[0]), "+f"(c[1]), "+f"(c[2]), "+f"(c[3])
        : "r"(a[0]), "r"(a[1]), "r"(a[2]), "r"(a[3]), "r"(b[0]), "r"(b[1]));
}

// ---------------- init / router / offs / scatter ----------------
__global__ void init_k() {
    int t = threadIdx.x;
    if (t < NE) { g_counts[t] = 0; g_Psum[t] = 0.f; }
}

__global__ __launch_bounds__(256) void router_k(const float* __restrict__ x,
                                                const float* __restrict__ gw) {
    int gtid = blockIdx.x * 256 + threadIdx.x;
    int tok  = gtid >> 5;
    int lane = gtid & 31;
    if (tok >= NTOK) return;
    const float* xr = x + (size_t)tok * DD;
    float acc[NE];
#pragma unroll
    for (int e = 0; e < NE; e++) acc[e] = 0.f;
    for (int d = lane; d < DD; d += 32) {
        float xv = xr[d];
        const float* g = gw + (size_t)d * NE;
#pragma unroll
        for (int e = 0; e < NE; e++) acc[e] += xv * g[e];
    }
#pragma unroll
    for (int e = 0; e < NE; e++)
#pragma unroll
        for (int off = 16; off; off >>= 1)
            acc[e] += __shfl_xor_sync(0xffffffffu, acc[e], off);
    if (lane == 0) {
        float l[NE]; float mx = -1e30f;
#pragma unroll
        for (int e = 0; e < NE; e++) { l[e] = acc[e] * 0.5f; mx = fmaxf(mx, l[e]); }
        int best = 0; float bv = l[0];
#pragma unroll
        for (int e = 1; e < NE; e++) if (l[e] > bv) { bv = l[e]; best = e; }
        g_idx[tok] = best;
        atomicAdd(&g_counts[best], 1);
        float p[NE]; float se = 0.f;
#pragma unroll
        for (int e = 0; e < NE; e++) { p[e] = expf(l[e] - mx); se += p[e]; }
        float inv = 1.f / se;
#pragma unroll
        for (int e = 0; e < NE; e++) atomicAdd(&g_Psum[e], p[e] * inv);
    }
}

__global__ void offs_k(float* __restrict__ dout, long long out_size) {
    if (threadIdx.x == 0 && blockIdx.x == 0) {
        int o = 0;
        for (int e = 0; e < NE; e++) { g_offs[e] = o; g_cursor[e] = o; o += g_counts[e]; }
        g_offs[NE] = o;
        float aux = 0.f;
        for (int e = 0; e < NE; e++) aux += (float)g_counts[e] * g_Psum[e];
        aux *= (float)NE / ((float)NTOK * (float)NTOK);
        if (out_size > (long long)NOUT) dout[NOUT] = aux;
    }
}

__global__ void scatter_k() {
    int t = blockIdx.x * 256 + threadIdx.x;
    if (t < NTOK) {
        int e = g_idx[t];
        int p = atomicAdd(&g_cursor[e], 1);
        g_sorted[p] = t;
    }
}

// ---------------- x -> tf32(RN) copy ----------------
__global__ __launch_bounds__(256) void xconv_k(const float* __restrict__ x, float* __restrict__ xc) {
    int i = blockIdx.x * 256 + threadIdx.x;
    if (i < NTOK * DD) xc[i] = rntf(x[i]);
}

// ---------------- weight transpose + tf32 round: src[e][K][N] -> dst[e][N][K] ----------------
__global__ __launch_bounds__(256) void transpose_k(const float* __restrict__ src,
                                                   float* __restrict__ dst, int K, int N) {
    __shared__ float t[32][33];
    const float* s = src + (size_t)blockIdx.z * K * N;
    float* d = dst + (size_t)blockIdx.z * K * N;
    int n0 = blockIdx.x * 32, k0 = blockIdx.y * 32;
    int tx = threadIdx.x, ty = threadIdx.y;
#pragma unroll
    for (int i = 0; i < 32; i += 8)
        t[ty + i][tx] = s[(size_t)(k0 + ty + i) * N + n0 + tx];
    __syncthreads();
#pragma unroll
    for (int i = 0; i < 32; i += 8)
        d[(size_t)(n0 + ty + i) * K + k0 + tx] = rntf(t[tx][ty + i]);
}

// ---------------- tf32 mma.sync GEMM ----------------
// D[m][n] = sum_k A[m][k] * BT[n][k]   (BT pre-transposed [N][K], tf32-rounded)
// Block tile 128x128x32, 8 warps (2 m-warps x 4 n-warps), warp tile 64x32.
// cp.async 2-stage pipeline. DUAL: shared A, two B and two accumulators.
// SWIGLU: out = silu(d1)*d2. CVTOUT: round outputs to tf32 (for use as next GEMM's A).
#define SROW 36
#define ATILE (128*SROW)
template<bool DUAL, bool SWIGLU, bool CVTOUT>
__global__ __launch_bounds__(256) void gemm_mma(
    const float* __restrict__ A,
    const float* __restrict__ B1, const float* __restrict__ B2, size_t strideB,
    float* __restrict__ C1, float* __restrict__ C2, int ldc, size_t strideC,
    int K, const int* __restrict__ sorted, const int* __restrict__ offs)
{
    extern __shared__ float sm[];
    __shared__ int rs[128];
    int e = blockIdx.z;
    int cnt; const int* rmap;
    if (offs) { int s0 = offs[e]; cnt = offs[e + 1] - s0; rmap = sorted + s0; }
    else      { cnt = NTOK; rmap = nullptr; }
    int m0 = blockIdx.y * 128;
    if (m0 >= cnt) return;
    int n0 = blockIdx.x * 128;
    const float* B1e = B1 + strideB * (size_t)e;
    const float* B2e = DUAL ? (B2 + strideB * (size_t)e) : nullptr;
    float* C1e = C1 + strideC * (size_t)e;
    float* C2e = (DUAL && !SWIGLU) ? (C2 + strideC * (size_t)e) : nullptr;

    int tid = threadIdx.x;
    if (tid < 128) {
        int ra = m0 + tid;
        int row = (ra < cnt) ? ra : (cnt - 1);
        rs[tid] = rmap ? rmap[row] : row;
    }
    __syncthreads();

    const int PERST = (DUAL ? 3 : 2) * ATILE;   // floats per stage
    uint32_t sbase = smem_u32(sm);

    // per-thread gmem/smem load slots: 4 x 16B each for A, B1, (B2)
    const float* aptr[4]; const float* b1p[4]; const float* b2p[4];
    uint32_t soA[4], soB1[4], soB2[4];
#pragma unroll
    for (int i = 0; i < 4; i++) {
        int f = i * 256 + tid;
        int r = f >> 3, c = f & 7;
        aptr[i] = A + (size_t)rs[r] * K + c * 4;
        b1p[i]  = B1e + (size_t)(n0 + r) * K + c * 4;
        if (DUAL) b2p[i] = B2e + (size_t)(n0 + r) * K + c * 4;
        uint32_t so = (uint32_t)(r * SROW + c * 4) * 4u;
        soA[i]  = sbase + so;
        soB1[i] = sbase + (uint32_t)ATILE * 4u + so;
        if (DUAL) soB2[i] = sbase + (uint32_t)(2 * ATILE) * 4u + so;
    }

    int lane = tid & 31, wid = tid >> 5;
    int g = lane >> 2, t4 = lane & 3;
    int wm = wid & 1, wn = wid >> 1;
    int mb0 = wm * 64, nb0 = wn * 32;

    float c1[4][4][4];
    float c2[DUAL ? 4 : 1][DUAL ? 4 : 1][4];
#pragma unroll
    for (int mf = 0; mf < 4; mf++)
#pragma unroll
        for (int nf = 0; nf < 4; nf++)
#pragma unroll
            for (int q = 0; q < 4; q++) {
                c1[mf][nf][q] = 0.f;
                if (DUAL) c2[mf][nf][q] = 0.f;
            }

    int NIT = K >> 5;

    auto load_tile = [&](int it, int st) {
        uint32_t sb = (uint32_t)(st * PERST) * 4u;
        int k0 = it << 5;
#pragma unroll
        for (int i = 0; i < 4; i++) cp16(soA[i] + sb, aptr[i] + k0);
#pragma unroll
        for (int i = 0; i < 4; i++) cp16(soB1[i] + sb, b1p[i] + k0);
        if (DUAL) {
#pragma unroll
            for (int i = 0; i < 4; i++) cp16(soB2[i] + sb, b2p[i] + k0);
        }
        cp_commit();
    };

    load_tile(0, 0);

    for (int it = 0; it < NIT; it++) {
        if (it + 1 < NIT) { load_tile(it + 1, (it + 1) & 1); cp_wait<1>(); }
        else              { cp_wait<0>(); }
        __syncthreads();

        const uint32_t* As  = (const uint32_t*)(sm + (it & 1) * PERST);
        const uint32_t* Bs1 = As + ATILE;
        const uint32_t* Bs2 = Bs1 + ATILE;

#pragma unroll
        for (int kk = 0; kk < 32; kk += 8) {
            uint32_t af[4][4];
#pragma unroll
            for (int mf = 0; mf < 4; mf++) {
                int ba = (mb0 + mf * 16 + g) * SROW + kk + t4;
                af[mf][0] = As[ba];
                af[mf][1] = As[ba + 8 * SROW];
                af[mf][2] = As[ba + 4];
                af[mf][3] = As[ba + 8 * SROW + 4];
            }
            uint32_t bf[4][2];
#pragma unroll
            for (int nf = 0; nf < 4; nf++) {
                int bb = (nb0 + nf * 8 + g) * SROW + kk + t4;
                bf[nf][0] = Bs1[bb];
                bf[nf][1] = Bs1[bb + 4];
            }
#pragma unroll
            for (int mf = 0; mf < 4; mf++)
#pragma unroll
                for (int nf = 0; nf < 4; nf++)
                    mma8(c1[mf][nf], af[mf], bf[nf]);
            if (DUAL) {
                uint32_t bg[4][2];
#pragma unroll
                for (int nf = 0; nf < 4; nf++) {
                    int bb = (nb0 + nf * 8 + g) * SROW + kk + t4;
                    bg[nf][0] = Bs2[bb];
                    bg[nf][1] = Bs2[bb + 4];
                }
#pragma unroll
                for (int mf = 0; mf < 4; mf++)
#pragma unroll
                    for (int nf = 0; nf < 4; nf++)
                        mma8(c2[mf][nf], af[mf], bg[nf]);
            }
        }
        __syncthreads();
    }

    // ---------------- epilogue ----------------
#pragma unroll
    for (int mf = 0; mf < 4; mf++) {
        int lr0 = mb0 + mf * 16 + g;
        int lr1 = lr0 + 8;
        bool v0 = (m0 + lr0) < cnt;
        bool v1 = (m0 + lr1) < cnt;
        float* p0 = C1e + (size_t)rs[lr0] * ldc + n0 + nb0;
        float* p1 = C1e + (size_t)rs[lr1] * ldc + n0 + nb0;
        float* q0 = nullptr; float* q1 = nullptr;
        if (DUAL && !SWIGLU) {
            q0 = C2e + (size_t)rs[lr0] * ldc + n0 + nb0;
            q1 = C2e + (size_t)rs[lr1] * ldc + n0 + nb0;
        }
#pragma unroll
        for (int nf = 0; nf < 4; nf++) {
            int co = nf * 8 + 2 * t4;
            float a0 = c1[mf][nf][0], a1 = c1[mf][nf][1];
            float a2 = c1[mf][nf][2], a3 = c1[mf][nf][3];
            if (SWIGLU) {
                float g0 = c2[mf][nf][0], g1 = c2[mf][nf][1];
                float g2 = c2[mf][nf][2], g3 = c2[mf][nf][3];
                a0 = a0 * g0 / (1.f + expf(-a0));
                a1 = a1 * g1 / (1.f + expf(-a1));
                a2 = a2 * g2 / (1.f + expf(-a2));
                a3 = a3 * g3 / (1.f + expf(-a3));
            }
            if (CVTOUT) { a0 = rntf(a0); a1 = rntf(a1); a2 = rntf(a2); a3 = rntf(a3); }
            if (v0) *(float2*)(p0 + co) = make_float2(a0, a1);
            if (v1) *(float2*)(p1 + co) = make_float2(a2, a3);
            if (DUAL && !SWIGLU) {
                float b0 = c2[mf][nf][0], b1v = c2[mf][nf][1];
                float b2v = c2[mf][nf][2], b3 = c2[mf][nf][3];
                if (v0) *(float2*)(q0 + co) = make_float2(b0, b1v);
                if (v1) *(float2*)(q1 + co) = make_float2(b2v, b3);
            }
        }
    }
}

// ---------------- mean key per (e,b) ----------------
__global__ void kbar_k() {
    int eb = blockIdx.x;
    const float* Kb = g_K + (size_t)eb * NL * DD;
    for (int d = threadIdx.x; d < DD; d += blockDim.x) {
        float s0 = 0.f, s1 = 0.f, s2 = 0.f, s3 = 0.f;
        for (int j = 0; j < NL; j += 4) {
            s0 += Kb[(size_t)(j+0)*DD + d];
            s1 += Kb[(size_t)(j+1)*DD + d];
            s2 += Kb[(size_t)(j+2)*DD + d];
            s3 += Kb[(size_t)(j+3)*DD + d];
        }
        g_kbar[(size_t)eb * DD + d] = (s0 + s1 + s2 + s3) * (1.f / (float)NL);
    }
}

// ---------------- sliding-window attention with Reynolds modulation ----------------
__global__ __launch_bounds__(384) void attn_k() {
    int token = blockIdx.x;
    int b = token >> 10;
    int t = token & (NL - 1);
    int e = g_idx[token];

    __shared__ float qs[DD];
    __shared__ float sc[NH][WINW + 4];
    __shared__ float mh[NH], invs[NH];

    int tid = threadIdx.x, lane = tid & 31, w = tid >> 5;
    for (int d = tid; d < DD; d += 384) qs[d] = g_Q[(size_t)token * DD + d];
    __syncthreads();

    int jlo = (t >= WINW - 1) ? t - (WINW - 1) : 0;
    int nj  = t - jlo + 1;
    size_t ebbase = (size_t)(e * NB + b) * NL * DD;
    const float* Kb = g_K + ebbase;

    int h = w;
    float q0 = qs[h*64 + lane*2], q1 = qs[h*64 + lane*2 + 1];

    for (int jj = 0; jj < nj; jj++) {
        const float* kr = Kb + (size_t)(jlo + jj) * DD + h*64 + lane*2;
        float p = q0 * kr[0] + q1 * kr[1];
#pragma unroll
        for (int off = 16; off; off >>= 1) p += __shfl_xor_sync(0xffffffffu, p, off);
        if (lane == 0) sc[h][jj] = p * 0.125f;
    }
    {
        const float* kb = g_kbar + (size_t)(e * NB + b) * DD + h*64 + lane*2;
        float p = q0 * kb[0] + q1 * kb[1];
#pragma unroll
        for (int off = 16; off; off >>= 1) p += __shfl_xor_sync(0xffffffffu, p, off);
        if (lane == 0) mh[h] = p * 0.125f;
    }
    __syncthreads();

    float m = mh[h];
    float mx = -1e30f;
    for (int jj = lane; jj < nj; jj += 32) {
        float sv = sc[h][jj];
        float sig = 1.f / (1.f + __expf(-sv));
        float sp = sv + 0.1f * sv - 0.1f * sig * sig - 0.1f * fabsf(sv - m);
        sc[h][jj] = sp;
        mx = fmaxf(mx, sp);
    }
#pragma unroll
    for (int off = 16; off; off >>= 1) mx = fmaxf(mx, __shfl_xor_sync(0xffffffffu, mx, off));
    float sum = 0.f;
    for (int jj = lane; jj < nj; jj += 32) {
        float pexp = __expf(sc[h][jj] - mx);
        sc[h][jj] = pexp;
        sum += pexp;
    }
#pragma unroll
    for (int off = 16; off; off >>= 1) sum += __shfl_xor_sync(0xffffffffu, sum, off);
    if (lane == 0) invs[h] = 1.f / sum;
    __syncthreads();

    const float* Vb = g_V + ebbase;
    for (int od = tid; od < DD; od += 384) {
        int hh = od >> 6;
        float acc = 0.f;
        for (int jj = 0; jj < nj; jj++)
            acc += sc[hh][jj] * Vb[(size_t)(jlo + jj) * DD + od];
        g_attn[(size_t)token * DD + od] = rntf(acc * invs[hh]);   // tf32-round: feeds SwiGLU GEMM
    }
}

// ---------------- launch ----------------
extern "C" void kernel_launch(void* const* d_in, const int* in_sizes, int n_in,
                              void* d_out, int out_size) {
    const float* x      = (const float*)d_in[0];
    const float* gate_w = (const float*)d_in[1];
    const float* q_w    = (const float*)d_in[2];
    const float* k_w    = (const float*)d_in[3];
    const float* v_w    = (const float*)d_in[4];
    const float* w1     = (const float*)d_in[5];
    const float* vg     = (const float*)d_in[6];
    const float* w2     = (const float*)d_in[7];
    const float* out_w  = (const float*)d_in[8];
    float* out = (float*)d_out;

    void *pK, *pV, *pQ, *pA, *pH, *pY, *pXC, *pS, *pO;
    void *pqT, *pkT, *pvT, *pw1T, *pvgT, *pw2T, *poT;
    cudaGetSymbolAddress(&pK, g_K);
    cudaGetSymbolAddress(&pV, g_V);
    cudaGetSymbolAddress(&pQ, g_Q);
    cudaGetSymbolAddress(&pA, g_attn);
    cudaGetSymbolAddress(&pH, g_Hb);
    cudaGetSymbolAddress(&pY, g_Y);
    cudaGetSymbolAddress(&pXC, g_xc);
    cudaGetSymbolAddress(&pS, g_sorted);
    cudaGetSymbolAddress(&pO, g_offs);
    cudaGetSymbolAddress(&pqT, g_qT);
    cudaGetSymbolAddress(&pkT, g_kT);
    cudaGetSymbolAddress(&pvT, g_vT);
    cudaGetSymbolAddress(&pw1T, g_w1T);
    cudaGetSymbolAddress(&pvgT, g_vgT);
    cudaGetSymbolAddress(&pw2T, g_w2T);
    cudaGetSymbolAddress(&poT, g_outT);
    const int* sortedp = (const int*)pS;
    const int* offsp   = (const int*)pO;
    const float* xc = (const float*)pXC;

    const int SM_SINGLE = 2 * 2 * ATILE * 4;   // 73728 B
    const int SM_DUAL   = 2 * 3 * ATILE * 4;   // 110592 B
    cudaFuncSetAttribute(gemm_mma<false,false,false>, cudaFuncAttributeMaxDynamicSharedMemorySize, SM_SINGLE);
    cudaFuncSetAttribute(gemm_mma<false,false,true >, cudaFuncAttributeMaxDynamicSharedMemorySize, SM_SINGLE);
    cudaFuncSetAttribute(gemm_mma<true, false,false>, cudaFuncAttributeMaxDynamicSharedMemorySize, SM_DUAL);
    cudaFuncSetAttribute(gemm_mma<true, true, true >, cudaFuncAttributeMaxDynamicSharedMemorySize, SM_DUAL);

    // weight transposes (+tf32 round) -> [N][K]
    transpose_k<<<dim3(24, 24, NE), dim3(32, 8)>>>(q_w,   (float*)pqT,  DD, DD);
    transpose_k<<<dim3(24, 24, NE), dim3(32, 8)>>>(k_w,   (float*)pkT,  DD, DD);
    transpose_k<<<dim3(24, 24, NE), dim3(32, 8)>>>(v_w,   (float*)pvT,  DD, DD);
    transpose_k<<<dim3(96, 24, NE), dim3(32, 8)>>>(w1,    (float*)pw1T, DD, FF);
    transpose_k<<<dim3(96, 24, NE), dim3(32, 8)>>>(vg,    (float*)pvgT, DD, FF);
    transpose_k<<<dim3(24, 96, NE), dim3(32, 8)>>>(w2,    (float*)pw2T, FF, DD);
    transpose_k<<<dim3(24, 24, 1),  dim3(32, 8)>>>(out_w, (float*)poT,  DD, DD);
    xconv_k<<<(NTOK * DD) / 256, 256>>>(x, (float*)pXC);

    init_k<<<1, 32>>>();
    router_k<<<NTOK / 8, 256>>>(x, gate_w);
    offs_k<<<1, 32>>>(out, (long long)out_size);
    scatter_k<<<NTOK / 256, 256>>>();

    // K & V for all experts (dense, dual-B, shared A)
    gemm_mma<true, false, false><<<dim3(DD/128, NTOK/128, NE), 256, SM_DUAL>>>(
        xc, (const float*)pkT, (const float*)pvT, (size_t)DD*DD,
        (float*)pK, (float*)pV, DD, (size_t)NTOK*DD, DD, nullptr, nullptr);
    kbar_k<<<NE * NB, 256>>>();

    // Q for routed expert (gathered)
    gemm_mma<false, false, false><<<dim3(DD/128, NTOK/128, NE), 256, SM_SINGLE>>>(
        xc, (const float*)pqT, nullptr, (size_t)DD*DD,
        (float*)pQ, nullptr, DD, 0, DD, sortedp, offsp);

    attn_k<<<NTOK, 384>>>();

    // SwiGLU up (fused dual GEMM + silu*gate, gathered; output tf32-rounded)
    gemm_mma<true, true, true><<<dim3(FF/128, NTOK/128, NE), 256, SM_DUAL>>>(
        (const float*)pA, (const float*)pw1T, (const float*)pvgT, (size_t)DD*FF,
        (float*)pH, nullptr, FF, 0, DD, sortedp, offsp);

    // down projection (gathered, K=3072; output tf32-rounded for final GEMM)
    gemm_mma<false, false, true><<<dim3(DD/128, NTOK/128, NE), 256, SM_SINGLE>>>(
        (const float*)pH, (const float*)pw2T, nullptr, (size_t)FF*DD,
        (float*)pY, nullptr, DD, 0, FF, sortedp, offsp);

    // final output projection (dense) -> d_out
    gemm_mma<false, false, false><<<dim3(DD/128, NTOK/128, 1), 256, SM_SINGLE>>>(
        (const float*)pY, (const float*)poT, nullptr, 0,
        out, nullptr, DD, 0, DD, nullptr, nullptr);
}

// round 4
// speedup vs baseline: 2.3698x; 1.1017x over previous
#include <cuda_runtime.h>
#include <math.h>
#include <stdint.h>

// ---------------- problem constants ----------------
#define DD    768
#define FF    3072
#define NE    8
#define NB    2
#define NL    1024
#define NTOK  2048
#define NH    12
#define HD    64
#define WINW  128
#define NOUT  (NTOK*DD)

// ---------------- device scratch ----------------
__device__ float g_K[NE*NTOK*DD];
__device__ float g_V[NE*NTOK*DD];
__device__ float g_Q[NTOK*DD];
__device__ float g_attn[NTOK*DD];
__device__ float g_Hb[NTOK*FF];
__device__ float g_Y[NTOK*DD];
__device__ float g_xc[NTOK*DD];       // x pre-rounded to tf32 (RN)
__device__ float g_kbar[NE*NB*DD];
__device__ int   g_idx[NTOK];
__device__ int   g_sorted[NTOK];
__device__ int   g_counts[NE];
__device__ int   g_cursor[NE];
__device__ int   g_offs[NE+1];
__device__ float g_Psum[NE];

// ---------------- PTX helpers (baseline PTX; no sm_103a-suffixed ops) ----------------
__device__ __forceinline__ uint32_t smem_u32(const void* p) {
    uint32_t a;
    asm("{ .reg .u64 t; cvta.to.shared.u64 t, %1; cvt.u32.u64 %0, t; }" : "=r"(a) : "l"(p));
    return a;
}
__device__ __forceinline__ void cp16(uint32_t s, const float* g) {
    asm volatile("cp.async.cg.shared.global [%0], [%1], 16;" :: "r"(s), "l"(g) : "memory");
}
__device__ __forceinline__ void cp_commit() {
    asm volatile("cp.async.commit_group;" ::: "memory");
}
template<int N> __device__ __forceinline__ void cp_wait() {
    asm volatile("cp.async.wait_group %0;" :: "n"(N) : "memory");
}
__device__ __forceinline__ float rntf(float v) {
    uint32_t o;
    asm("cvt.rna.tf32.f32 %0, %1;" : "=r"(o) : "f"(v));
    return __uint_as_float(o);
}
__device__ __forceinline__ void mma8(float* c, const uint32_t* a, const uint32_t* b) {
    asm volatile("mma.sync.aligned.m16n8k8.row.col.f32.tf32.tf32.f32 "
        "{%0,%1,%2,%3}, {%4,%5,%6,%7}, {%8,%9}, {%0,%1,%2,%3};"
        : "+f"(c[0]), "+f"(c[1]), "+f"(c[2]), "+f"(c[3])
        : "r"(a[0]), "r"(a[1]), "r"(a[2]), "r"(a[3]), "r"(b[0]), "r"(b[1]));
}
__device__ __forceinline__ void ldsm4(uint32_t* r, uint32_t addr) {
    asm volatile("ldmatrix.sync.aligned.m8n8.x4.shared.b16 {%0,%1,%2,%3}, [%4];"
        : "=r"(r[0]), "=r"(r[1]), "=r"(r[2]), "=r"(r[3]) : "r"(addr));
}

// ---------------- init / router / offs / scatter ----------------
__global__ void init_k() {
    int t = threadIdx.x;
    if (t < NE) { g_counts[t] = 0; g_Psum[t] = 0.f; }
}

__global__ __launch_bounds__(256) void router_k(const float* __restrict__ x,
                                                const float* __restrict__ gw) {
    int gtid = blockIdx.x * 256 + threadIdx.x;
    int tok  = gtid >> 5;
    int lane = gtid & 31;
    if (tok >= NTOK) return;
    const float* xr = x + (size_t)tok * DD;
    float acc[NE];
#pragma unroll
    for (int e = 0; e < NE; e++) acc[e] = 0.f;
    for (int d = lane; d < DD; d += 32) {
        float xv = xr[d];
        const float* g = gw + (size_t)d * NE;
#pragma unroll
        for (int e = 0; e < NE; e++) acc[e] += xv * g[e];
    }
#pragma unroll
    for (int e = 0; e < NE; e++)
#pragma unroll
        for (int off = 16; off; off >>= 1)
            acc[e] += __shfl_xor_sync(0xffffffffu, acc[e], off);
    if (lane == 0) {
        float l[NE]; float mx = -1e30f;
#pragma unroll
        for (int e = 0; e < NE; e++) { l[e] = acc[e] * 0.5f; mx = fmaxf(mx, l[e]); }
        int best = 0; float bv = l[0];
#pragma unroll
        for (int e = 1; e < NE; e++) if (l[e] > bv) { bv = l[e]; best = e; }
        g_idx[tok] = best;
        atomicAdd(&g_counts[best], 1);
        float p[NE]; float se = 0.f;
#pragma unroll
        for (int e = 0; e < NE; e++) { p[e] = expf(l[e] - mx); se += p[e]; }
        float inv = 1.f / se;
#pragma unroll
        for (int e = 0; e < NE; e++) atomicAdd(&g_Psum[e], p[e] * inv);
    }
}

__global__ void offs_k(float* __restrict__ dout, long long out_size) {
    if (threadIdx.x == 0 && blockIdx.x == 0) {
        int o = 0;
        for (int e = 0; e < NE; e++) { g_offs[e] = o; g_cursor[e] = o; o += g_counts[e]; }
        g_offs[NE] = o;
        float aux = 0.f;
        for (int e = 0; e < NE; e++) aux += (float)g_counts[e] * g_Psum[e];
        aux *= (float)NE / ((float)NTOK * (float)NTOK);
        if (out_size > (long long)NOUT) dout[NOUT] = aux;
    }
}

__global__ void scatter_k() {
    int t = blockIdx.x * 256 + threadIdx.x;
    if (t < NTOK) {
        int e = g_idx[t];
        int p = atomicAdd(&g_cursor[e], 1);
        g_sorted[p] = t;
    }
}

// ---------------- x -> tf32(RN) copy ----------------
__global__ __launch_bounds__(256) void xconv_k(const float* __restrict__ x, float* __restrict__ xc) {
    int i = blockIdx.x * 256 + threadIdx.x;
    if (i < NTOK * DD) xc[i] = rntf(x[i]);
}

// ---------------- tf32 mma.sync GEMM, B read directly from [K][N] weights ----------------
// D[m][n] = sum_k A[m][k] * B[k][n]
// Block tile 128x128x32, 8 warps (2 m x 4 n), warp tile 64x32, 3-stage cp.async.
// A smem: 128 rows x 128B, XOR-swizzled 16B chunks, read via ldmatrix.x4.
// B smem: [32 k][136 n-pad] floats, direct conflict-free LDS; tf32-rounded in-register.
// DUAL: shared A, two B / two accumulators. SWIGLU: out = silu(d1)*d2.
// CVTOUT: round outputs to tf32 (they feed a later GEMM's A operand).
#define AFL   4096                       // A floats per stage
#define BFL   (32*136)                   // B floats per stage (4352)
#define ABYTES (AFL*4)
#define BBYTES (BFL*4)
template<bool DUAL, bool SWIGLU, bool CVTOUT>
__global__ __launch_bounds__(256) void gemm_mma(
    const float* __restrict__ A,
    const float* __restrict__ B1, const float* __restrict__ B2,
    int ldb, size_t strideB,
    float* __restrict__ C1, float* __restrict__ C2, int ldc, size_t strideC,
    int K, const int* __restrict__ sorted, const int* __restrict__ offs)
{
    extern __shared__ float sm[];
    __shared__ int rs[128];
    int e = blockIdx.z;
    int cnt; const int* rmap;
    if (offs) { int s0 = offs[e]; cnt = offs[e + 1] - s0; rmap = sorted + s0; }
    else      { cnt = NTOK; rmap = nullptr; }
    int m0 = blockIdx.y * 128;
    if (m0 >= cnt) return;
    int n0 = blockIdx.x * 128;
    const float* B1e = B1 + strideB * (size_t)e;
    const float* B2e = DUAL ? (B2 + strideB * (size_t)e) : nullptr;
    float* C1e = C1 + strideC * (size_t)e;
    float* C2e = (DUAL && !SWIGLU) ? (C2 + strideC * (size_t)e) : nullptr;

    int tid = threadIdx.x;
    if (tid < 128) {
        int ra = m0 + tid;
        int row = (ra < cnt) ? ra : (cnt - 1);
        rs[tid] = rmap ? rmap[row] : row;
    }
    __syncthreads();

    const uint32_t PERSTB = (uint32_t)(ABYTES + (DUAL ? 2 : 1) * BBYTES);
    uint32_t sbase = smem_u32(sm);

    // per-thread load slots
    const float* aptr[4]; const float* b1p[4]; const float* b2p[4];
    uint32_t soA[4], soB[4];
#pragma unroll
    for (int i = 0; i < 4; i++) {
        int f = i * 256 + tid;
        int ar = f >> 3, ac = f & 7;                 // A: row, 16B-chunk
        aptr[i] = A + (size_t)rs[ar] * K + ac * 4;
        soA[i]  = sbase + (uint32_t)(ar * 128 + ((ac ^ (ar & 7)) << 4));
        int kr = f >> 5, nc = f & 31;                // B: k-row, 16B-chunk in n
        b1p[i]  = B1e + (size_t)kr * ldb + n0 + nc * 4;
        if (DUAL) b2p[i] = B2e + (size_t)kr * ldb + n0 + nc * 4;
        soB[i]  = sbase + (uint32_t)ABYTES + (uint32_t)((kr * 136 + nc * 4) * 4);
    }

    int lane = tid & 31, wid = tid >> 5;
    int g = lane >> 2, t4 = lane & 3;
    int wm = wid & 1, wn = wid >> 1;
    int mb0 = wm * 64, nb0 = wn * 32;
    int lrow = mb0 + (lane & 15);                    // ldmatrix row base
    int lx = lane & 7, lhi = lane >> 4;

    float c1[4][4][4];
    float c2[DUAL ? 4 : 1][DUAL ? 4 : 1][4];
#pragma unroll
    for (int mf = 0; mf < 4; mf++)
#pragma unroll
        for (int nf = 0; nf < 4; nf++)
#pragma unroll
            for (int q = 0; q < 4; q++) {
                c1[mf][nf][q] = 0.f;
                if (DUAL) c2[mf][nf][q] = 0.f;
            }

    int NIT = K >> 5;

    auto load_tile = [&](int it, int st) {
        uint32_t sb = (uint32_t)st * PERSTB;
        int k0 = it << 5;
        size_t bk = (size_t)k0 * ldb;
#pragma unroll
        for (int i = 0; i < 4; i++) cp16(soA[i] + sb, aptr[i] + k0);
#pragma unroll
        for (int i = 0; i < 4; i++) cp16(soB[i] + sb, b1p[i] + bk);
        if (DUAL) {
#pragma unroll
            for (int i = 0; i < 4; i++) cp16(soB[i] + sb + (uint32_t)BBYTES, b2p[i] + bk);
        }
        cp_commit();
    };

    load_tile(0, 0);
    load_tile(1, 1);

    for (int it = 0; it < NIT; it++) {
        if (it == NIT - 1) cp_wait<0>(); else cp_wait<1>();
        __syncthreads();
        int st = it % 3;
        uint32_t Ast = sbase + (uint32_t)st * PERSTB;
        const float* Bst1 = sm + (size_t)st * (PERSTB >> 2) + AFL;
        const float* Bst2 = Bst1 + BFL;

#pragma unroll
        for (int kk = 0; kk < 32; kk += 8) {
            int c0 = kk >> 2;
            uint32_t af[4][4];
#pragma unroll
            for (int mf = 0; mf < 4; mf++) {
                uint32_t addr = Ast + (uint32_t)((lrow + 16 * mf) * 128 + (((c0 + lhi) ^ lx) << 4));
                ldsm4(af[mf], addr);
            }
            uint32_t bf[4][2];
#pragma unroll
            for (int nf = 0; nf < 4; nf++) {
                int bb = (kk + t4) * 136 + nb0 + nf * 8 + g;
                bf[nf][0] = __float_as_uint(rntf(Bst1[bb]));
                bf[nf][1] = __float_as_uint(rntf(Bst1[bb + 4 * 136]));
            }
#pragma unroll
            for (int mf = 0; mf < 4; mf++)
#pragma unroll
                for (int nf = 0; nf < 4; nf++)
                    mma8(c1[mf][nf], af[mf], bf[nf]);
            if (DUAL) {
                uint32_t bg[4][2];
#pragma unroll
                for (int nf = 0; nf < 4; nf++) {
                    int bb = (kk + t4) * 136 + nb0 + nf * 8 + g;
                    bg[nf][0] = __float_as_uint(rntf(Bst2[bb]));
                    bg[nf][1] = __float_as_uint(rntf(Bst2[bb + 4 * 136]));
                }
#pragma unroll
                for (int mf = 0; mf < 4; mf++)
#pragma unroll
                    for (int nf = 0; nf < 4; nf++)
                        mma8(c2[mf][nf], af[mf], bg[nf]);
            }
        }
        if (it + 2 < NIT) load_tile(it + 2, (it + 2) % 3);
    }

    // ---------------- epilogue ----------------
#pragma unroll
    for (int mf = 0; mf < 4; mf++) {
        int lr0 = mb0 + mf * 16 + g;
        int lr1 = lr0 + 8;
        bool v0 = (m0 + lr0) < cnt;
        bool v1 = (m0 + lr1) < cnt;
        float* p0 = C1e + (size_t)rs[lr0] * ldc + n0 + nb0;
        float* p1 = C1e + (size_t)rs[lr1] * ldc + n0 + nb0;
        float* q0 = nullptr; float* q1 = nullptr;
        if (DUAL && !SWIGLU) {
            q0 = C2e + (size_t)rs[lr0] * ldc + n0 + nb0;
            q1 = C2e + (size_t)rs[lr1] * ldc + n0 + nb0;
        }
#pragma unroll
        for (int nf = 0; nf < 4; nf++) {
            int co = nf * 8 + 2 * t4;
            float a0 = c1[mf][nf][0], a1 = c1[mf][nf][1];
            float a2 = c1[mf][nf][2], a3 = c1[mf][nf][3];
            if (SWIGLU) {
                float g0 = c2[mf][nf][0], g1 = c2[mf][nf][1];
                float g2 = c2[mf][nf][2], g3 = c2[mf][nf][3];
                a0 = a0 * g0 / (1.f + expf(-a0));
                a1 = a1 * g1 / (1.f + expf(-a1));
                a2 = a2 * g2 / (1.f + expf(-a2));
                a3 = a3 * g3 / (1.f + expf(-a3));
            }
            if (CVTOUT) { a0 = rntf(a0); a1 = rntf(a1); a2 = rntf(a2); a3 = rntf(a3); }
            if (v0) *(float2*)(p0 + co) = make_float2(a0, a1);
            if (v1) *(float2*)(p1 + co) = make_float2(a2, a3);
            if (DUAL && !SWIGLU) {
                float b0 = c2[mf][nf][0], b1v = c2[mf][nf][1];
                float b2v = c2[mf][nf][2], b3 = c2[mf][nf][3];
                if (v0) *(float2*)(q0 + co) = make_float2(b0, b1v);
                if (v1) *(float2*)(q1 + co) = make_float2(b2v, b3);
            }
        }
    }
}

// ---------------- mean key per (e,b) ----------------
__global__ void kbar_k() {
    int eb = blockIdx.x;
    const float* Kb = g_K + (size_t)eb * NL * DD;
    for (int d = threadIdx.x; d < DD; d += blockDim.x) {
        float s0 = 0.f, s1 = 0.f, s2 = 0.f, s3 = 0.f;
        for (int j = 0; j < NL; j += 4) {
            s0 += Kb[(size_t)(j+0)*DD + d];
            s1 += Kb[(size_t)(j+1)*DD + d];
            s2 += Kb[(size_t)(j+2)*DD + d];
            s3 += Kb[(size_t)(j+3)*DD + d];
        }
        g_kbar[(size_t)eb * DD + d] = (s0 + s1 + s2 + s3) * (1.f / (float)NL);
    }
}

// ---------------- sliding-window attention with Reynolds modulation ----------------
// One block per token; 12 warps = 12 heads. K window staged via smem tiles.
#define KTPAD 772
__global__ __launch_bounds__(384) void attn_k() {
    int token = blockIdx.x;
    int b = token >> 10;
    int t = token & (NL - 1);
    int e = g_idx[token];

    __shared__ float qs[DD];
    __shared__ float sc[NH][WINW + 4];
    __shared__ float mh[NH], invs[NH];
    __shared__ float ks[16][KTPAD];

    int tid = threadIdx.x, lane = tid & 31, h = tid >> 5;
    for (int d = tid; d < DD; d += 384) qs[d] = g_Q[(size_t)token * DD + d];
    __syncthreads();

    int jlo = (t >= WINW - 1) ? t - (WINW - 1) : 0;
    int nj  = t - jlo + 1;
    size_t ebbase = (size_t)(e * NB + b) * NL * DD;
    const float* Kb = g_K + ebbase;

    // full-row mean via mean key (linearity of dot)
    {
        const float* kb = g_kbar + (size_t)(e * NB + b) * DD + h*64 + lane*2;
        float q0 = qs[h*64 + lane*2], q1 = qs[h*64 + lane*2 + 1];
        float p = q0 * kb[0] + q1 * kb[1];
#pragma unroll
        for (int off = 16; off; off >>= 1) p += __shfl_xor_sync(0xffffffffu, p, off);
        if (lane == 0) mh[h] = p * 0.125f;
    }

    // raw scores over the window, K staged through smem in 16-row tiles
    int j2 = lane >> 1, half = lane & 1;
    const float* qr = &qs[h*64 + half*32];
    int ntile = (nj + 15) >> 4;
    for (int tt = 0; tt < ntile; tt++) {
        int j0 = tt << 4;
        int rows = nj - j0; if (rows > 16) rows = 16;
        for (int v = tid; v < rows * 192; v += 384) {
            int r = v / 192, c4 = v % 192;
            *(float4*)&ks[r][c4 * 4] = *(const float4*)(Kb + (size_t)(jlo + j0 + r) * DD + c4 * 4);
        }
        __syncthreads();
        const float* kr = &ks[j2][h*64 + half*32];
        float s = 0.f;
#pragma unroll
        for (int i = 0; i < 32; i++) s += qr[i] * kr[i];
        s += __shfl_xor_sync(0xffffffffu, s, 1);
        if (half == 0 && j2 < rows) sc[h][j0 + j2] = s * 0.125f;
        __syncthreads();
    }

    // Reynolds modulation + softmax over valid window
    float m = mh[h];
    float mx = -1e30f;
    for (int jj = lane; jj < nj; jj += 32) {
        float sv = sc[h][jj];
        float sig = 1.f / (1.f + __expf(-sv));
        float sp = sv + 0.1f * sv - 0.1f * sig * sig - 0.1f * fabsf(sv - m);
        sc[h][jj] = sp;
        mx = fmaxf(mx, sp);
    }
#pragma unroll
    for (int off = 16; off; off >>= 1) mx = fmaxf(mx, __shfl_xor_sync(0xffffffffu, mx, off));
    float sum = 0.f;
    for (int jj = lane; jj < nj; jj += 32) {
        float pexp = __expf(sc[h][jj] - mx);
        sc[h][jj] = pexp;
        sum += pexp;
    }
#pragma unroll
    for (int off = 16; off; off >>= 1) sum += __shfl_xor_sync(0xffffffffu, sum, off);
    if (lane == 0) invs[h] = 1.f / sum;
    __syncthreads();

    // out = attn @ V (coalesced over d, 4-way j unroll for MLP)
    const float* Vb = g_V + ebbase;
    for (int od = tid; od < DD; od += 384) {
        int hh = od >> 6;
        const float* vb = Vb + (size_t)jlo * DD + od;
        float a0 = 0.f, a1 = 0.f, a2 = 0.f, a3 = 0.f;
        int j = 0;
        for (; j + 4 <= nj; j += 4) {
            a0 += sc[hh][j+0] * vb[(size_t)(j+0)*DD];
            a1 += sc[hh][j+1] * vb[(size_t)(j+1)*DD];
            a2 += sc[hh][j+2] * vb[(size_t)(j+2)*DD];
            a3 += sc[hh][j+3] * vb[(size_t)(j+3)*DD];
        }
        for (; j < nj; j++) a0 += sc[hh][j] * vb[(size_t)j*DD];
        g_attn[(size_t)token * DD + od] = rntf((a0 + a1 + a2 + a3) * invs[hh]);
    }
}

// ---------------- launch ----------------
extern "C" void kernel_launch(void* const* d_in, const int* in_sizes, int n_in,
                              void* d_out, int out_size) {
    const float* x      = (const float*)d_in[0];
    const float* gate_w = (const float*)d_in[1];
    const float* q_w    = (const float*)d_in[2];
    const float* k_w    = (const float*)d_in[3];
    const float* v_w    = (const float*)d_in[4];
    const float* w1     = (const float*)d_in[5];
    const float* vg     = (const float*)d_in[6];
    const float* w2     = (const float*)d_in[7];
    const float* out_w  = (const float*)d_in[8];
    float* out = (float*)d_out;

    void *pK, *pV, *pQ, *pA, *pH, *pY, *pXC, *pS, *pO;
    cudaGetSymbolAddress(&pK, g_K);
    cudaGetSymbolAddress(&pV, g_V);
    cudaGetSymbolAddress(&pQ, g_Q);
    cudaGetSymbolAddress(&pA, g_attn);
    cudaGetSymbolAddress(&pH, g_Hb);
    cudaGetSymbolAddress(&pY, g_Y);
    cudaGetSymbolAddress(&pXC, g_xc);
    cudaGetSymbolAddress(&pS, g_sorted);
    cudaGetSymbolAddress(&pO, g_offs);
    const int* sortedp = (const int*)pS;
    const int* offsp   = (const int*)pO;
    const float* xc = (const float*)pXC;

    const int SM_SINGLE = 3 * (ABYTES + BBYTES);       // 101376 B
    const int SM_DUAL   = 3 * (ABYTES + 2 * BBYTES);   // 153600 B
    cudaFuncSetAttribute(gemm_mma<false,false,false>, cudaFuncAttributeMaxDynamicSharedMemorySize, SM_SINGLE);
    cudaFuncSetAttribute(gemm_mma<false,false,true >, cudaFuncAttributeMaxDynamicSharedMemorySize, SM_SINGLE);
    cudaFuncSetAttribute(gemm_mma<true, false,false>, cudaFuncAttributeMaxDynamicSharedMemorySize, SM_DUAL);
    cudaFuncSetAttribute(gemm_mma<true, true, true >, cudaFuncAttributeMaxDynamicSharedMemorySize, SM_DUAL);

    xconv_k<<<(NTOK * DD) / 256, 256>>>(x, (float*)pXC);
    init_k<<<1, 32>>>();
    router_k<<<NTOK / 8, 256>>>(x, gate_w);
    offs_k<<<1, 32>>>(out, (long long)out_size);
    scatter_k<<<NTOK / 256, 256>>>();

    // K & V for all experts (dense, dual-B, shared A)
    gemm_mma<true, false, false><<<dim3(DD/128, NTOK/128, NE), 256, SM_DUAL>>>(
        xc, k_w, v_w, DD, (size_t)DD*DD,
        (float*)pK, (float*)pV, DD, (size_t)NTOK*DD, DD, nullptr, nullptr);
    kbar_k<<<NE * NB, 256>>>();

    // Q for routed expert (gathered)
    gemm_mma<false, false, false><<<dim3(DD/128, NTOK/128, NE), 256, SM_SINGLE>>>(
        xc, q_w, nullptr, DD, (size_t)DD*DD,
        (float*)pQ, nullptr, DD, 0, DD, sortedp, offsp);

    attn_k<<<NTOK, 384>>>();

    // SwiGLU up (fused dual GEMM + silu*gate, gathered; output tf32-rounded)
    gemm_mma<true, true, true><<<dim3(FF/128, NTOK/128, NE), 256, SM_DUAL>>>(
        (const float*)pA, w1, vg, FF, (size_t)DD*FF,
        (float*)pH, nullptr, FF, 0, DD, sortedp, offsp);

    // down projection (gathered, K=3072; output tf32-rounded for final GEMM)
    gemm_mma<false, false, true><<<dim3(DD/128, NTOK/128, NE), 256, SM_SINGLE>>>(
        (const float*)pH, w2, nullptr, DD, (size_t)FF*DD,
        (float*)pY, nullptr, DD, 0, FF, sortedp, offsp);

    // final output projection (dense) -> d_out
    gemm_mma<false, false, false><<<dim3(DD/128, NTOK/128, 1), 256, SM_SINGLE>>>(
        (const float*)pY, out_w, nullptr, DD, 0,
        out, nullptr, DD, 0, DD, nullptr, nullptr);
}

// round 8
// speedup vs baseline: 2.4997x; 1.0548x over previous
#include <cuda_runtime.h>
#include <math.h>
#include <stdint.h>

// ---------------- problem constants ----------------
#define DD    768
#define FF    3072
#define NE    8
#define NB    2
#define NL    1024
#define NTOK  2048
#define NH    12
#define HD    64
#define WINW  128
#define NOUT  (NTOK*DD)

// ---------------- device scratch ----------------
__device__ float g_K[NE*NTOK*DD];
__device__ float g_V[NE*NTOK*DD];
__device__ float g_Q[NTOK*DD];
__device__ float g_attn[NTOK*DD];
__device__ float g_Hb[NTOK*FF];
__device__ float g_Y[NTOK*DD];
__device__ float g_xc[NTOK*DD];       // x pre-rounded to tf32 (RN)
__device__ float g_xbar[NB*DD];
__device__ float g_kbar[NE*NB*DD];
__device__ int   g_idx[NTOK];
__device__ int   g_sorted[NTOK];
__device__ int   g_counts[NE];
__device__ int   g_cursor[NE];
__device__ int   g_offs[NE+1];
__device__ float g_Psum[NE];

// ---------------- PTX helpers (baseline PTX; no sm_103a-suffixed ops) ----------------
__device__ __forceinline__ uint32_t smem_u32(const void* p) {
    uint32_t a;
    asm("{ .reg .u64 t; cvta.to.shared.u64 t, %1; cvt.u32.u64 %0, t; }" : "=r"(a) : "l"(p));
    return a;
}
__device__ __forceinline__ void cp16(uint32_t s, const float* g) {
    asm volatile("cp.async.cg.shared.global [%0], [%1], 16;" :: "r"(s), "l"(g) : "memory");
}
__device__ __forceinline__ void cp_commit() {
    asm volatile("cp.async.commit_group;" ::: "memory");
}
template<int N> __device__ __forceinline__ void cp_wait() {
    asm volatile("cp.async.wait_group %0;" :: "n"(N) : "memory");
}
__device__ __forceinline__ float rntf(float v) {
    uint32_t o;
    asm("cvt.rna.tf32.f32 %0, %1;" : "=r"(o) : "f"(v));
    return __uint_as_float(o);
}
__device__ __forceinline__ void mma8(float* c, const uint32_t* a, const uint32_t* b) {
    asm volatile("mma.sync.aligned.m16n8k8.row.col.f32.tf32.tf32.f32 "
        "{%0,%1,%2,%3}, {%4,%5,%6,%7}, {%8,%9}, {%0,%1,%2,%3};"
        : "+f"(c[0]), "+f"(c[1]), "+f"(c[2]), "+f"(c[3])
        : "r"(a[0]), "r"(a[1]), "r"(a[2]), "r"(a[3]), "r"(b[0]), "r"(b[1]));
}
__device__ __forceinline__ void ldsm4(uint32_t* r, uint32_t addr) {
    asm volatile("ldmatrix.sync.aligned.m8n8.x4.shared.b16 {%0,%1,%2,%3}, [%4];"
        : "=r"(r[0]), "=r"(r[1]), "=r"(r[2]), "=r"(r[3]) : "r"(addr));
}

// ---------------- init / router / offs / scatter ----------------
__global__ void init_k() {
    int t = threadIdx.x;
    if (t < NE) { g_counts[t] = 0; g_Psum[t] = 0.f; }
}

__global__ __launch_bounds__(256) void router_k(const float* __restrict__ x,
                                                const float* __restrict__ gw) {
    int gtid = blockIdx.x * 256 + threadIdx.x;
    int tok  = gtid >> 5;
    int lane = gtid & 31;
    if (tok >= NTOK) return;
    const float* xr = x + (size_t)tok * DD;
    float acc[NE];
#pragma unroll
    for (int e = 0; e < NE; e++) acc[e] = 0.f;
    for (int d = lane; d < DD; d += 32) {
        float xv = xr[d];
        const float* g = gw + (size_t)d * NE;
#pragma unroll
        for (int e = 0; e < NE; e++) acc[e] += xv * g[e];
    }
#pragma unroll
    for (int e = 0; e < NE; e++)
#pragma unroll
        for (int off = 16; off; off >>= 1)
            acc[e] += __shfl_xor_sync(0xffffffffu, acc[e], off);
    if (lane == 0) {
        float l[NE]; float mx = -1e30f;
#pragma unroll
        for (int e = 0; e < NE; e++) { l[e] = acc[e] * 0.5f; mx = fmaxf(mx, l[e]); }
        int best = 0; float bv = l[0];
#pragma unroll
        for (int e = 1; e < NE; e++) if (l[e] > bv) { bv = l[e]; best = e; }
        g_idx[tok] = best;
        atomicAdd(&g_counts[best], 1);
        float p[NE]; float se = 0.f;
#pragma unroll
        for (int e = 0; e < NE; e++) { p[e] = expf(l[e] - mx); se += p[e]; }
        float inv = 1.f / se;
#pragma unroll
        for (int e = 0; e < NE; e++) atomicAdd(&g_Psum[e], p[e] * inv);
    }
}

__global__ void offs_k(float* __restrict__ dout, long long out_size) {
    if (threadIdx.x == 0 && blockIdx.x == 0) {
        int o = 0;
        for (int e = 0; e < NE; e++) { g_offs[e] = o; g_cursor[e] = o; o += g_counts[e]; }
        g_offs[NE] = o;
        float aux = 0.f;
        for (int e = 0; e < NE; e++) aux += (float)g_counts[e] * g_Psum[e];
        aux *= (float)NE / ((float)NTOK * (float)NTOK);
        if (out_size > (long long)NOUT) dout[NOUT] = aux;
    }
}

__global__ void scatter_k() {
    int t = blockIdx.x * 256 + threadIdx.x;
    if (t < NTOK) {
        int e = g_idx[t];
        int p = atomicAdd(&g_cursor[e], 1);
        g_sorted[p] = t;
    }
}

// ---------------- x -> tf32(RN) copy ----------------
__global__ __launch_bounds__(256) void xconv_k(const float* __restrict__ x, float* __restrict__ xc) {
    int i = blockIdx.x * 256 + threadIdx.x;
    if (i < NTOK * DD) xc[i] = rntf(x[i]);
}

// ---------------- x column means per batch ----------------
__global__ __launch_bounds__(256) void xbar_k(const float* __restrict__ x) {
    int b = blockIdx.x;
    for (int d = threadIdx.x; d < DD; d += 256) {
        float s = 0.f;
        const float* xb = x + (size_t)b * NL * DD + d;
        for (int j = 0; j < NL; j++) s += xb[(size_t)j * DD];
        g_xbar[b * DD + d] = s * (1.f / (float)NL);
    }
}

// ---------------- kbar[e,b,:] = xbar[b,:] @ k_w[e] ----------------
__global__ __launch_bounds__(256) void kbar2_k(const float* __restrict__ k_w) {
    int e = blockIdx.x;
    __shared__ float xs[NB * DD];
    for (int i = threadIdx.x; i < NB * DD; i += 256) xs[i] = g_xbar[i];
    __syncthreads();
    const float* W = k_w + (size_t)e * DD * DD;
    for (int d = threadIdx.x; d < DD; d += 256) {
        float a0 = 0.f, a1 = 0.f;
        for (int dk = 0; dk < DD; dk++) {
            float w = W[(size_t)dk * DD + d];
            a0 += xs[dk] * w;
            a1 += xs[DD + dk] * w;
        }
        g_kbar[(e * NB + 0) * DD + d] = a0;
        g_kbar[(e * NB + 1) * DD + d] = a1;
    }
}

// ---------------- slot descriptor for the unified GEMM ----------------
struct Slot {
    const float* B;            // weight base [K][N], row-major, ld = ldb
    float* C;                  // output base
    unsigned long long strideB;  // per-expert stride in B
    unsigned long long strideC;  // per-expert stride in C
    int gather;                // use sorted/offs row map
};

// ---------------- unified tf32 mma.sync GEMM (single B, 2 CTAs/SM) ----------------
// D[m][n] = sum_k A[m][k] * B[k][n]
// Block tile 128x128x32, 8 warps (2 m x 4 n), warp tile 64x32, 3-stage cp.async.
// A smem: 128 rows x 128B, XOR-swizzled, ldmatrix.x4. B smem: [32][136] floats.
// blockIdx.x selects slot (bx/nbx) and n-tile (bx%nbx).
// SWIGLU_EPI: out = silu(z)*acc with z read from zbuf at the same location.
// CVTOUT: round outputs to tf32 (feeds a later GEMM's A operand).
#define AFL   4096
#define BFL   (32*136)
#define ABYTES (AFL*4)
#define BBYTES (BFL*4)
#define PERSTB ((uint32_t)(ABYTES + BBYTES))
template<bool SWIGLU_EPI, bool CVTOUT>
__global__ __launch_bounds__(256, 2) void gemm1(
    const float* __restrict__ A, int ldb, int ldc, int K, int nbx,
    Slot s0, Slot s1, Slot s2,
    const int* __restrict__ sorted, const int* __restrict__ offs,
    const float* __restrict__ zbuf)
{
    extern __shared__ float sm[];
    __shared__ int rs[128];
    int which = blockIdx.x / nbx;
    int n0 = (blockIdx.x - which * nbx) * 128;
    const float* Bb; float* Cb; unsigned long long sB, sC; int gat;
    if (which == 0)      { Bb = s0.B; Cb = s0.C; sB = s0.strideB; sC = s0.strideC; gat = s0.gather; }
    else if (which == 1) { Bb = s1.B; Cb = s1.C; sB = s1.strideB; sC = s1.strideC; gat = s1.gather; }
    else                 { Bb = s2.B; Cb = s2.C; sB = s2.strideB; sC = s2.strideC; gat = s2.gather; }
    int e = blockIdx.z;
    int cnt; const int* rmap;
    if (gat) { int st0 = offs[e]; cnt = offs[e + 1] - st0; rmap = sorted + st0; }
    else     { cnt = NTOK; rmap = nullptr; }
    int m0 = blockIdx.y * 128;
    if (m0 >= cnt) return;
    const float* Be = Bb + sB * (size_t)e;
    float* Ce = Cb + sC * (size_t)e;

    int tid = threadIdx.x;
    if (tid < 128) {
        int ra = m0 + tid;
        int row = (ra < cnt) ? ra : (cnt - 1);
        rs[tid] = rmap ? rmap[row] : row;
    }
    __syncthreads();

    uint32_t sbase = smem_u32(sm);

    const float* aptr[4]; const float* bp[4];
    uint32_t soA[4], soB[4];
#pragma unroll
    for (int i = 0; i < 4; i++) {
        int f = i * 256 + tid;
        int ar = f >> 3, ac = f & 7;
        aptr[i] = A + (size_t)rs[ar] * K + ac * 4;
        soA[i]  = sbase + (uint32_t)(ar * 128 + ((ac ^ (ar & 7)) << 4));
        int kr = f >> 5, nc = f & 31;
        bp[i]   = Be + (size_t)kr * ldb + n0 + nc * 4;
        soB[i]  = sbase + (uint32_t)ABYTES + (uint32_t)((kr * 136 + nc * 4) * 4);
    }

    int lane = tid & 31, wid = tid >> 5;
    int g = lane >> 2, t4 = lane & 3;
    int wm = wid & 1, wn = wid >> 1;
    int mb0 = wm * 64, nb0 = wn * 32;
    int lrow = mb0 + (lane & 15);
    int lx = lane & 7, lhi = lane >> 4;

    float c1[4][4][4];
#pragma unroll
    for (int mf = 0; mf < 4; mf++)
#pragma unroll
        for (int nf = 0; nf < 4; nf++)
#pragma unroll
            for (int q = 0; q < 4; q++) c1[mf][nf][q] = 0.f;

    int NIT = K >> 5;

    auto load_tile = [&](int it, int st) {
        uint32_t sb = (uint32_t)st * PERSTB;
        int k0 = it << 5;
        size_t bk = (size_t)k0 * ldb;
#pragma unroll
        for (int i = 0; i < 4; i++) cp16(soA[i] + sb, aptr[i] + k0);
#pragma unroll
        for (int i = 0; i < 4; i++) cp16(soB[i] + sb, bp[i] + bk);
        cp_commit();
    };

    load_tile(0, 0);
    load_tile(1, 1);

    for (int it = 0; it < NIT; it++) {
        if (it == NIT - 1) cp_wait<0>(); else cp_wait<1>();
        __syncthreads();
        int st = it % 3;
        uint32_t Ast = sbase + (uint32_t)st * PERSTB;
        const float* Bst = sm + (size_t)st * (PERSTB >> 2) + AFL;

#pragma unroll
        for (int kk = 0; kk < 32; kk += 8) {
            int c0 = kk >> 2;
            uint32_t af[4][4];
#pragma unroll
            for (int mf = 0; mf < 4; mf++) {
                uint32_t addr = Ast + (uint32_t)((lrow + 16 * mf) * 128 + (((c0 + lhi) ^ lx) << 4));
                ldsm4(af[mf], addr);
            }
            uint32_t bf[4][2];
#pragma unroll
            for (int nf = 0; nf < 4; nf++) {
                int bb = (kk + t4) * 136 + nb0 + nf * 8 + g;
                bf[nf][0] = __float_as_uint(rntf(Bst[bb]));
                bf[nf][1] = __float_as_uint(rntf(Bst[bb + 4 * 136]));
            }
#pragma unroll
            for (int mf = 0; mf < 4; mf++)
#pragma unroll
                for (int nf = 0; nf < 4; nf++)
                    mma8(c1[mf][nf], af[mf], bf[nf]);
        }
        if (it + 2 < NIT) load_tile(it + 2, (it + 2) % 3);
    }

    // ---------------- epilogue ----------------
#pragma unroll
    for (int mf = 0; mf < 4; mf++) {
        int lr0 = mb0 + mf * 16 + g;
        int lr1 = lr0 + 8;
        bool v0 = (m0 + lr0) < cnt;
        bool v1 = (m0 + lr1) < cnt;
        float* p0 = Ce + (size_t)rs[lr0] * ldc + n0 + nb0;
        float* p1 = Ce + (size_t)rs[lr1] * ldc + n0 + nb0;
        const float* z0p = nullptr; const float* z1p = nullptr;
        if (SWIGLU_EPI) {
            z0p = zbuf + (size_t)rs[lr0] * ldc + n0 + nb0;
            z1p = zbuf + (size_t)rs[lr1] * ldc + n0 + nb0;
        }
#pragma unroll
        for (int nf = 0; nf < 4; nf++) {
            int co = nf * 8 + 2 * t4;
            float a0 = c1[mf][nf][0], a1 = c1[mf][nf][1];
            float a2 = c1[mf][nf][2], a3 = c1[mf][nf][3];
            if (SWIGLU_EPI) {
                float2 za = v0 ? *(const float2*)(z0p + co) : make_float2(0.f, 0.f);
                float2 zb = v1 ? *(const float2*)(z1p + co) : make_float2(0.f, 0.f);
                a0 = za.x / (1.f + expf(-za.x)) * a0;
                a1 = za.y / (1.f + expf(-za.y)) * a1;
                a2 = zb.x / (1.f + expf(-zb.x)) * a2;
                a3 = zb.y / (1.f + expf(-zb.y)) * a3;
            }
            if (CVTOUT) { a0 = rntf(a0); a1 = rntf(a1); a2 = rntf(a2); a3 = rntf(a3); }
            if (v0) *(float2*)(p0 + co) = make_float2(a0, a1);
            if (v1) *(float2*)(p1 + co) = make_float2(a2, a3);
        }
    }
}

// ---------------- sliding-window attention with Reynolds modulation ----------------
// KTPAD must keep row stride a multiple of 16 bytes (float4 staging): 772*4=3088 ok.
#define KTPAD 772
__global__ __launch_bounds__(384) void attn_k() {
    int token = blockIdx.x;
    int b = token >> 10;
    int t = token & (NL - 1);
    int e = g_idx[token];

    __shared__ float qs[DD];
    __shared__ float sc[NH][WINW + 4];
    __shared__ float mh[NH], invs[NH];
    __shared__ float ks[16][KTPAD];

    int tid = threadIdx.x, lane = tid & 31, h = tid >> 5;
    for (int d = tid; d < DD; d += 384) qs[d] = g_Q[(size_t)token * DD + d];
    __syncthreads();

    int jlo = (t >= WINW - 1) ? t - (WINW - 1) : 0;
    int nj  = t - jlo + 1;
    size_t ebbase = (size_t)(e * NB + b) * NL * DD;
    const float* Kb = g_K + ebbase;

    // full-row mean via mean key (linearity of dot)
    {
        const float* kb = g_kbar + (size_t)(e * NB + b) * DD + h*64 + lane*2;
        float q0 = qs[h*64 + lane*2], q1 = qs[h*64 + lane*2 + 1];
        float p = q0 * kb[0] + q1 * kb[1];
#pragma unroll
        for (int off = 16; off; off >>= 1) p += __shfl_xor_sync(0xffffffffu, p, off);
        if (lane == 0) mh[h] = p * 0.125f;
    }

    // raw scores over the window, K staged through smem in 16-row tiles
    int j2 = lane >> 1, half = lane & 1;
    const float* qr = &qs[h*64 + half*32];
    int ntile = (nj + 15) >> 4;
    for (int tt = 0; tt < ntile; tt++) {
        int j0 = tt << 4;
        int rows = nj - j0; if (rows > 16) rows = 16;
        for (int v = tid; v < rows * 192; v += 384) {
            int r = v / 192, c4 = v % 192;
            *(float4*)&ks[r][c4 * 4] = *(const float4*)(Kb + (size_t)(jlo + j0 + r) * DD + c4 * 4);
        }
        __syncthreads();
        const float* kr = &ks[j2][h*64 + half*32];
        float s = 0.f;
#pragma unroll
        for (int i = 0; i < 32; i++) s += qr[i] * kr[i];
        s += __shfl_xor_sync(0xffffffffu, s, 1);
        if (half == 0 && j2 < rows) sc[h][j0 + j2] = s * 0.125f;
        __syncthreads();
    }

    // Reynolds modulation + softmax over valid window
    float m = mh[h];
    float mx = -1e30f;
    for (int jj = lane; jj < nj; jj += 32) {
        float sv = sc[h][jj];
        float sig = 1.f / (1.f + __expf(-sv));
        float sp = sv + 0.1f * sv - 0.1f * sig * sig - 0.1f * fabsf(sv - m);
        sc[h][jj] = sp;
        mx = fmaxf(mx, sp);
    }
#pragma unroll
    for (int off = 16; off; off >>= 1) mx = fmaxf(mx, __shfl_xor_sync(0xffffffffu, mx, off));
    float sum = 0.f;
    for (int jj = lane; jj < nj; jj += 32) {
        float pexp = __expf(sc[h][jj] - mx);
        sc[h][jj] = pexp;
        sum += pexp;
    }
#pragma unroll
    for (int off = 16; off; off >>= 1) sum += __shfl_xor_sync(0xffffffffu, sum, off);
    if (lane == 0) invs[h] = 1.f / sum;
    __syncthreads();

    // out = attn @ V (coalesced over d, 4-way j unroll)
    const float* Vb = g_V + ebbase;
    for (int od = tid; od < DD; od += 384) {
        int hh = od >> 6;
        const float* vb = Vb + (size_t)jlo * DD + od;
        float a0 = 0.f, a1 = 0.f, a2 = 0.f, a3 = 0.f;
        int j = 0;
        for (; j + 4 <= nj; j += 4) {
            a0 += sc[hh][j+0] * vb[(size_t)(j+0)*DD];
            a1 += sc[hh][j+1] * vb[(size_t)(j+1)*DD];
            a2 += sc[hh][j+2] * vb[(size_t)(j+2)*DD];
            a3 += sc[hh][j+3] * vb[(size_t)(j+3)*DD];
        }
        for (; j < nj; j++) a0 += sc[hh][j] * vb[(size_t)j*DD];
        g_attn[(size_t)token * DD + od] = rntf((a0 + a1 + a2 + a3) * invs[hh]);
    }
}

// ---------------- launch ----------------
extern "C" void kernel_launch(void* const* d_in, const int* in_sizes, int n_in,
                              void* d_out, int out_size) {
    const float* x      = (const float*)d_in[0];
    const float* gate_w = (const float*)d_in[1];
    const float* q_w    = (const float*)d_in[2];
    const float* k_w    = (const float*)d_in[3];
    const float* v_w    = (const float*)d_in[4];
    const float* w1     = (const float*)d_in[5];
    const float* vg     = (const float*)d_in[6];
    const float* w2     = (const float*)d_in[7];
    const float* out_w  = (const float*)d_in[8];
    float* out = (float*)d_out;

    void *pK, *pV, *pQ, *pA, *pH, *pY, *pXC, *pS, *pO;
    cudaGetSymbolAddress(&pK, g_K);
    cudaGetSymbolAddress(&pV, g_V);
    cudaGetSymbolAddress(&pQ, g_Q);
    cudaGetSymbolAddress(&pA, g_attn);
    cudaGetSymbolAddress(&pH, g_Hb);
    cudaGetSymbolAddress(&pY, g_Y);
    cudaGetSymbolAddress(&pXC, g_xc);
    cudaGetSymbolAddress(&pS, g_sorted);
    cudaGetSymbolAddress(&pO, g_offs);
    const int* sortedp = (const int*)pS;
    const int* offsp   = (const int*)pO;
    const float* xc = (const float*)pXC;

    const int SM_B = 3 * (ABYTES + BBYTES);   // 101376 B
    cudaFuncSetAttribute(gemm1<false,false>, cudaFuncAttributeMaxDynamicSharedMemorySize, SM_B);
    cudaFuncSetAttribute(gemm1<false,true >, cudaFuncAttributeMaxDynamicSharedMemorySize, SM_B);
    cudaFuncSetAttribute(gemm1<true, true >, cudaFuncAttributeMaxDynamicSharedMemorySize, SM_B);

    xconv_k<<<(NTOK * DD) / 256, 256>>>(x, (float*)pXC);
    init_k<<<1, 32>>>();
    router_k<<<NTOK / 8, 256>>>(x, gate_w);
    offs_k<<<1, 32>>>(out, (long long)out_size);
    scatter_k<<<NTOK / 256, 256>>>();
    xbar_k<<<NB, 256>>>(x);
    kbar2_k<<<NE, 256>>>(k_w);

    Slot sK  = { k_w,  (float*)pK, (unsigned long long)DD*DD, (unsigned long long)NTOK*DD, 0 };
    Slot sV  = { v_w,  (float*)pV, (unsigned long long)DD*DD, (unsigned long long)NTOK*DD, 0 };
    Slot sQ  = { q_w,  (float*)pQ, (unsigned long long)DD*DD, 0ull, 1 };
    Slot sW1 = { w1,   (float*)pH, (unsigned long long)DD*FF, 0ull, 1 };
    Slot sVG = { vg,   (float*)pH, (unsigned long long)DD*FF, 0ull, 1 };
    Slot sW2 = { w2,   (float*)pY, (unsigned long long)FF*DD, 0ull, 1 };
    Slot sOW = { out_w, out, 0ull, 0ull, 0 };

    // K, V (dense) and Q (gathered) in ONE launch: slot = blockIdx.x / 6
    gemm1<false,false><<<dim3(18, 16, 8), 256, SM_B>>>(
        xc, DD, DD, DD, 6, sK, sV, sQ, sortedp, offsp, nullptr);

    attn_k<<<NTOK, 384>>>();

    // SwiGLU: z = attn @ w1 (raw), then h = silu(z) * (attn @ vg), in-place on g_Hb
    gemm1<false,false><<<dim3(24, 16, 8), 256, SM_B>>>(
        (const float*)pA, FF, FF, DD, 24, sW1, sW1, sW1, sortedp, offsp, nullptr);
    gemm1<true,true><<<dim3(24, 16, 8), 256, SM_B>>>(
        (const float*)pA, FF, FF, DD, 24, sVG, sVG, sVG, sortedp, offsp, (const float*)pH);

    // down projection (gathered, K=3072)
    gemm1<false,true><<<dim3(6, 16, 8), 256, SM_B>>>(
        (const float*)pH, DD, DD, FF, 6, sW2, sW2, sW2, sortedp, offsp, nullptr);

    // final output projection (dense) -> d_out
    gemm1<false,false><<<dim3(6, 16, 1), 256, SM_B>>>(
        (const float*)pY, DD, DD, DD, 6, sOW, sOW, sOW, sortedp, offsp, nullptr);
}